// round 16
// baseline (speedup 1.0000x reference)
#include <cuda_runtime.h>
#include <cuda_bf16.h>

#define Nn 50000
#define Ee 640000
#define Hh 128
#define NWT 40000            // Ee / 16 edge warp-tiles
#define EGRID 148
#define EWARPS 12
#define NNT 3125             // Nn / 16 node warp-tiles

// ---------------- device-global scratch (no allocs allowed) ----------------
__device__ __align__(16) float g_msg[Nn * Hh];
__device__ __align__(16) float g_hs[Nn * Hh];   // h @ We1[0:128] + be1
__device__ __align__(16) float g_hd[Nn * Hh];   // h @ We1[128:256]
// B images, mma fragment order.
// Interleaved layout (hi/lo): uint4 at [kt*2048 + nt*128 + lane*4]:
//   .x=hi reg0, .y=hi reg1, .z=lo reg0, .w=lo reg1
__device__ __align__(16) unsigned g_We2i[16384];   // perm-K, 8 kt
__device__ __align__(16) unsigned g_Wc1h[8192];    // natural, hi only (2-pass GEMM2)
__device__ __align__(16) unsigned g_Wn1i[32768];   // perm-K, 16 kt (K=256)
__device__ __align__(16) unsigned g_Wn2i[16384];   // natural, 8 kt
__device__ __align__(16) unsigned g_We1i[2][16384];// perm-K, 8 kt (top/bottom halves)

__device__ __forceinline__ float silu_f(float v) {
    return __fdividef(v, 1.f + __expf(-v));
}

// ---------------- cp.async ----------------
__device__ __forceinline__ void cp_async16(void* dst, const void* src) {
    unsigned u = (unsigned)__cvta_generic_to_shared(dst);
    asm volatile("cp.async.ca.shared.global [%0], [%1], 16;" :: "r"(u), "l"(src));
}
__device__ __forceinline__ void cp_commit() { asm volatile("cp.async.commit_group;"); }
template<int P> __device__ __forceinline__ void cp_wait() {
    asm volatile("cp.async.wait_group %0;" :: "n"(P));
}

// ---------------- warp mma ----------------
__device__ __forceinline__ void mma_bf16(float* c, const unsigned* a,
                                         unsigned b0, unsigned b1) {
    asm volatile(
        "mma.sync.aligned.m16n8k16.row.col.f32.bf16.bf16.f32 "
        "{%0,%1,%2,%3}, {%4,%5,%6,%7}, {%8,%9}, {%0,%1,%2,%3};"
        : "+f"(c[0]), "+f"(c[1]), "+f"(c[2]), "+f"(c[3])
        : "r"(a[0]), "r"(a[1]), "r"(a[2]), "r"(a[3]), "r"(b0), "r"(b1));
}

__device__ __forceinline__ unsigned pack_bf2(float x, float y) {
    __nv_bfloat162 t = __floats2bfloat162_rn(x, y);
    return *(unsigned*)&t;
}
__device__ __forceinline__ void split2(float x, float y, unsigned& hi, unsigned& lo) {
    __nv_bfloat16 hx = __float2bfloat16(x), hy = __float2bfloat16(y);
    hi = (unsigned)__bfloat16_as_ushort(hx) | ((unsigned)__bfloat16_as_ushort(hy) << 16);
    lo = pack_bf2(x - __bfloat162float(hx), y - __bfloat162float(hy));
}

// ---------------------------------------------------------------------------
__global__ void init_kernel(const float* __restrict__ x, float* __restrict__ xo) {
    int idx = blockIdx.x * 256 + threadIdx.x;
    if (idx < Nn * 3) xo[idx] = x[idx];
    if (idx < Nn * Hh) g_msg[idx] = 0.f;
}

// K-permutation: MMA invariant when A and B use the same K reorder; perm makes
// each lane's 4 A-values per kt one contiguous float4 at orig col kt*16+4*t4.

// edge weights: We2 interleaved perm-K; Wc1 natural hi-only
__global__ void prep_edge_kernel(const float* __restrict__ We2, const float* __restrict__ Wc1) {
    int idx = blockIdx.x * 256 + threadIdx.x;
    if (idx >= 16384) return;
    int t    = idx & 8191;
    int reg  = t & 1;
    int lane = (t >> 1) & 31;
    int nt   = (t >> 6) & 15;
    int kt   = t >> 10;
    int n    = nt * 8 + (lane >> 2);
    if (idx < 8192) {        // We2, perm-K, interleaved
        int k0 = kt * 16 + (lane & 3) * 4 + reg * 2;
        float w0 = We2[k0 * Hh + n];
        float w1 = We2[(k0 + 1) * Hh + n];
        unsigned hi, lo; split2(w0, w1, hi, lo);
        int base = kt * 2048 + nt * 128 + lane * 4;
        g_We2i[base + reg]     = hi;
        g_We2i[base + 2 + reg] = lo;
    } else {                 // Wc1, natural, hi only
        int k0 = kt * 16 + reg * 8 + (lane & 3) * 2;
        float w0 = Wc1[k0 * Hh + n];
        float w1 = Wc1[(k0 + 1) * Hh + n];
        unsigned hi, lo; split2(w0, w1, hi, lo);
        g_Wc1h[kt * 1024 + nt * 64 + lane * 2 + reg] = hi;
    }
}

// node weights: Wn1 interleaved perm-K (K=256); Wn2 interleaved natural
__global__ void prep_node_kernel(const float* __restrict__ Wn1, const float* __restrict__ Wn2) {
    int idx = blockIdx.x * 256 + threadIdx.x;
    if (idx < 16384) {       // Wn1
        int reg = idx & 1, lane = (idx >> 1) & 31, nt = (idx >> 6) & 15, kt = idx >> 10;
        int n  = nt * 8 + (lane >> 2);
        int k0 = kt * 16 + (lane & 3) * 4 + reg * 2;
        float w0 = Wn1[k0 * Hh + n];
        float w1 = Wn1[(k0 + 1) * Hh + n];
        unsigned hi, lo; split2(w0, w1, hi, lo);
        int base = kt * 2048 + nt * 128 + lane * 4;
        g_Wn1i[base + reg]     = hi;
        g_Wn1i[base + 2 + reg] = lo;
    } else if (idx < 24576) { // Wn2
        int t = idx - 16384;
        int reg = t & 1, lane = (t >> 1) & 31, nt = (t >> 6) & 15, kt = t >> 10;
        int n  = nt * 8 + (lane >> 2);
        int k0 = kt * 16 + reg * 8 + (lane & 3) * 2;
        float w0 = Wn2[k0 * Hh + n];
        float w1 = Wn2[(k0 + 1) * Hh + n];
        unsigned hi, lo; split2(w0, w1, hi, lo);
        int base = kt * 2048 + nt * 128 + lane * 4;
        g_Wn2i[base + reg]     = hi;
        g_Wn2i[base + 2 + reg] = lo;
    }
}

// pre weights: We1 top/bottom halves, interleaved perm-K
__global__ void prep_pre_kernel(const float* __restrict__ We1) {
    int idx = blockIdx.x * 256 + threadIdx.x;
    if (idx >= 16384) return;
    int mat  = idx >> 13;
    int t    = idx & 8191;
    int reg  = t & 1;
    int lane = (t >> 1) & 31;
    int nt   = (t >> 6) & 15;
    int kt   = t >> 10;
    int n    = nt * 8 + (lane >> 2);
    int k0   = kt * 16 + (lane & 3) * 4 + reg * 2;
    const float* W = We1 + (size_t)mat * 128 * Hh;
    float w0 = W[k0 * Hh + n];
    float w1 = W[(k0 + 1) * Hh + n];
    unsigned hi, lo; split2(w0, w1, hi, lo);
    int base = kt * 2048 + nt * 128 + lane * 4;
    g_We1i[mat][base + reg]     = hi;
    g_We1i[mat][base + 2 + reg] = lo;
}

// ---------------------------------------------------------------------------
// pre kernel (mma): g_hs = h @ We1_top + be1 ; g_hd = h @ We1_bot
__global__ __launch_bounds__(32 * EWARPS) void pre_kernel_mma(
    const float* __restrict__ h, const float* __restrict__ be1)
{
    extern __shared__ unsigned su[];
    float* sBe1 = (float*)(su + 32768);

    const int tid  = threadIdx.x;
    const int wid  = tid >> 5;
    const int lane = tid & 31;
    const int g    = lane >> 2;
    const int t4   = lane & 3;

    for (int i = tid; i < 16384 / 4; i += 32 * EWARPS) {
        cp_async16(su + i * 4, g_We1i[0] + i * 4);
        cp_async16(su + 16384 + i * 4, g_We1i[1] + i * 4);
    }
    cp_commit();
    if (tid < 128) sBe1[tid] = be1[tid];
    cp_wait<0>();
    __syncthreads();

    for (int wt = blockIdx.x * EWARPS + wid; wt < NNT; wt += EGRID * EWARPS) {
        const int na = wt * 16 + g;
        const int nb = na + 8;
        const float* pa = h + (size_t)na * Hh;
        const float* pb = h + (size_t)nb * Hh;

        // A fragments from h (perm-K float4 loads), built once
        unsigned aHi[8][4], aLo[8][4];
#pragma unroll
        for (int kt = 0; kt < 8; kt++) {
            float4 va = *(const float4*)(pa + kt * 16 + 4 * t4);
            float4 vb = *(const float4*)(pb + kt * 16 + 4 * t4);
            split2(va.x, va.y, aHi[kt][0], aLo[kt][0]);
            split2(va.z, va.w, aHi[kt][2], aLo[kt][2]);
            split2(vb.x, vb.y, aHi[kt][1], aLo[kt][1]);
            split2(vb.z, vb.w, aHi[kt][3], aLo[kt][3]);
        }

        float acc[16][4];

        // GEMM-a: hs = h @ We1_top (3-pass), + be1
#pragma unroll
        for (int nt = 0; nt < 16; nt++)
#pragma unroll
            for (int j = 0; j < 4; j++) acc[nt][j] = 0.f;
#pragma unroll
        for (int kt = 0; kt < 8; kt++) {
            const unsigned* bi = su + kt * 2048 + lane * 4;
#pragma unroll
            for (int nt = 0; nt < 16; nt++) {
                uint4 b = *(const uint4*)(bi + nt * 128);
                mma_bf16(acc[nt], aHi[kt], b.x, b.y);
                mma_bf16(acc[nt], aHi[kt], b.z, b.w);
                mma_bf16(acc[nt], aLo[kt], b.x, b.y);
            }
        }
#pragma unroll
        for (int nt = 0; nt < 16; nt++) {
            int c = nt * 8 + 2 * t4;
            float2 o0, o1;
            o0.x = acc[nt][0] + sBe1[c];     o0.y = acc[nt][1] + sBe1[c + 1];
            o1.x = acc[nt][2] + sBe1[c];     o1.y = acc[nt][3] + sBe1[c + 1];
            *(float2*)(g_hs + (size_t)na * Hh + c) = o0;
            *(float2*)(g_hs + (size_t)nb * Hh + c) = o1;
        }

        // GEMM-b: hd = h @ We1_bot (3-pass)
#pragma unroll
        for (int nt = 0; nt < 16; nt++)
#pragma unroll
            for (int j = 0; j < 4; j++) acc[nt][j] = 0.f;
#pragma unroll
        for (int kt = 0; kt < 8; kt++) {
            const unsigned* bi = su + 16384 + kt * 2048 + lane * 4;
#pragma unroll
            for (int nt = 0; nt < 16; nt++) {
                uint4 b = *(const uint4*)(bi + nt * 128);
                mma_bf16(acc[nt], aHi[kt], b.x, b.y);
                mma_bf16(acc[nt], aHi[kt], b.z, b.w);
                mma_bf16(acc[nt], aLo[kt], b.x, b.y);
            }
        }
#pragma unroll
        for (int nt = 0; nt < 16; nt++) {
            int c = nt * 8 + 2 * t4;
            float2 o0, o1;
            o0.x = acc[nt][0]; o0.y = acc[nt][1];
            o1.x = acc[nt][2]; o1.y = acc[nt][3];
            *(float2*)(g_hd + (size_t)na * Hh + c) = o0;
            *(float2*)(g_hd + (size_t)nb * Hh + c) = o1;
        }
    }
}

// ---------------------------------------------------------------------------
// tensor edge kernel: warp-autonomous, 12 warps, interleaved GEMM1 B loads.
#define SM_META_E  24576                   // uints: 16384 (We2i) + 8192 (Wc1h)
__global__ __launch_bounds__(32 * EWARPS) void edge_kernel_mma(
    const float* __restrict__ x, const int* __restrict__ ei,
    const float* __restrict__ We1,
    const float* __restrict__ be2, const float* __restrict__ bc1,
    const float* __restrict__ Wc2, float* __restrict__ xo)
{
    extern __shared__ unsigned su[];
    float* sW256 = (float*)(su + SM_META_E);
    float* sBe2  = sW256 + 128;
    float* sBc1  = sBe2 + 128;
    float* sWc2  = sBc1 + 128;

    const int tid  = threadIdx.x;
    const int wid  = tid >> 5;
    const int lane = tid & 31;
    const int g    = lane >> 2;
    const int t4   = lane & 3;

    for (int i = tid; i < 16384 / 4; i += 32 * EWARPS)
        cp_async16(su + i * 4, g_We2i + i * 4);
    for (int i = tid; i < 8192 / 4; i += 32 * EWARPS)
        cp_async16(su + 16384 + i * 4, g_Wc1h + i * 4);
    cp_commit();
    if (tid < 128) {
        sW256[tid] = We1[256 * Hh + tid];
        sBe2[tid]  = be2[tid];
        sBc1[tid]  = bc1[tid];
        sWc2[tid]  = Wc2[tid];
    }
    cp_wait<0>();
    __syncthreads();

    const int gwarp = blockIdx.x * EWARPS + wid;

    for (int wt = gwarp; wt < NWT; wt += EGRID * EWARPS) {
        const int ge0 = wt * 16 + g;
        const int ge1 = ge0 + 8;
        const int s0 = ei[ge0], d0 = ei[Ee + ge0];
        const int s1 = ei[ge1], d1 = ei[Ee + ge1];
        float rx0 = x[s0 * 3 + 0] - x[d0 * 3 + 0];
        float ry0 = x[s0 * 3 + 1] - x[d0 * 3 + 1];
        float rz0 = x[s0 * 3 + 2] - x[d0 * 3 + 2];
        float rx1 = x[s1 * 3 + 0] - x[d1 * 3 + 0];
        float ry1 = x[s1 * 3 + 1] - x[d1 * 3 + 1];
        float rz1 = x[s1 * 3 + 2] - x[d1 * 3 + 2];
        const float d2_0 = rx0 * rx0 + ry0 * ry0 + rz0 * rz0;
        const float d2_1 = rx1 * rx1 + ry1 * ry1 + rz1 * rz1;

        // layer-1 gather (perm-K float4s) -> A fragments
        unsigned aHi[8][4], aLo[8][4];
        {
            float4 s4[8], d4[8];
#pragma unroll
            for (int kt = 0; kt < 8; kt++) {
                s4[kt] = *(const float4*)(g_hs + (size_t)s0 * Hh + kt * 16 + 4 * t4);
                d4[kt] = *(const float4*)(g_hd + (size_t)d0 * Hh + kt * 16 + 4 * t4);
            }
#pragma unroll
            for (int kt = 0; kt < 8; kt++) {
                float4 w = *(const float4*)(sW256 + kt * 16 + 4 * t4);
                split2(silu_f(s4[kt].x + d4[kt].x + d2_0 * w.x),
                       silu_f(s4[kt].y + d4[kt].y + d2_0 * w.y), aHi[kt][0], aLo[kt][0]);
                split2(silu_f(s4[kt].z + d4[kt].z + d2_0 * w.z),
                       silu_f(s4[kt].w + d4[kt].w + d2_0 * w.w), aHi[kt][2], aLo[kt][2]);
            }
#pragma unroll
            for (int kt = 0; kt < 8; kt++) {
                s4[kt] = *(const float4*)(g_hs + (size_t)s1 * Hh + kt * 16 + 4 * t4);
                d4[kt] = *(const float4*)(g_hd + (size_t)d1 * Hh + kt * 16 + 4 * t4);
            }
#pragma unroll
            for (int kt = 0; kt < 8; kt++) {
                float4 w = *(const float4*)(sW256 + kt * 16 + 4 * t4);
                split2(silu_f(s4[kt].x + d4[kt].x + d2_1 * w.x),
                       silu_f(s4[kt].y + d4[kt].y + d2_1 * w.y), aHi[kt][1], aLo[kt][1]);
                split2(silu_f(s4[kt].z + d4[kt].z + d2_1 * w.z),
                       silu_f(s4[kt].w + d4[kt].w + d2_1 * w.w), aHi[kt][3], aLo[kt][3]);
            }
        }

        // GEMM1 (interleaved We2i, 3-pass)
        float acc[16][4];
#pragma unroll
        for (int nt = 0; nt < 16; nt++)
#pragma unroll
            for (int j = 0; j < 4; j++) acc[nt][j] = 0.f;
#pragma unroll
        for (int kt = 0; kt < 8; kt++) {
            const unsigned* bi = su + kt * 2048 + lane * 4;
#pragma unroll
            for (int nt = 0; nt < 16; nt++) {
                uint4 b = *(const uint4*)(bi + nt * 128);
                mma_bf16(acc[nt], aHi[kt], b.x, b.y);
                mma_bf16(acc[nt], aHi[kt], b.z, b.w);
                mma_bf16(acc[nt], aLo[kt], b.x, b.y);
            }
        }

        // epilogue 1: silu, scatter, repack
        float* msg0 = g_msg + (size_t)d0 * Hh;
        float* msg1 = g_msg + (size_t)d1 * Hh;
#pragma unroll
        for (int kt = 0; kt < 8; kt++) {
            int c = kt * 16 + 2 * t4;
            float m00 = silu_f(acc[2 * kt][0]     + sBe2[c]);
            float m01 = silu_f(acc[2 * kt][1]     + sBe2[c + 1]);
            float m10 = silu_f(acc[2 * kt][2]     + sBe2[c]);
            float m11 = silu_f(acc[2 * kt][3]     + sBe2[c + 1]);
            float m02 = silu_f(acc[2 * kt + 1][0] + sBe2[c + 8]);
            float m03 = silu_f(acc[2 * kt + 1][1] + sBe2[c + 9]);
            float m12 = silu_f(acc[2 * kt + 1][2] + sBe2[c + 8]);
            float m13 = silu_f(acc[2 * kt + 1][3] + sBe2[c + 9]);
            asm volatile("red.global.add.v2.f32 [%0], {%1, %2};"
                         :: "l"(msg0 + c),     "f"(m00), "f"(m01) : "memory");
            asm volatile("red.global.add.v2.f32 [%0], {%1, %2};"
                         :: "l"(msg0 + c + 8), "f"(m02), "f"(m03) : "memory");
            asm volatile("red.global.add.v2.f32 [%0], {%1, %2};"
                         :: "l"(msg1 + c),     "f"(m10), "f"(m11) : "memory");
            asm volatile("red.global.add.v2.f32 [%0], {%1, %2};"
                         :: "l"(msg1 + c + 8), "f"(m12), "f"(m13) : "memory");
            split2(m00, m01, aHi[kt][0], aLo[kt][0]);
            split2(m10, m11, aHi[kt][1], aLo[kt][1]);
            split2(m02, m03, aHi[kt][2], aLo[kt][2]);
            split2(m12, m13, aHi[kt][3], aLo[kt][3]);
        }

        // GEMM2 (natural Wc1 hi, 2-pass)
#pragma unroll
        for (int nt = 0; nt < 16; nt++)
#pragma unroll
            for (int j = 0; j < 4; j++) acc[nt][j] = 0.f;
#pragma unroll
        for (int kt = 0; kt < 8; kt++) {
            const unsigned* bh = su + 16384 + kt * 1024 + lane * 2;
#pragma unroll
            for (int nt = 0; nt < 16; nt++) {
                uint2 bH = *(const uint2*)(bh + nt * 64);
                mma_bf16(acc[nt], aHi[kt], bH.x, bH.y);
                mma_bf16(acc[nt], aLo[kt], bH.x, bH.y);
            }
        }

        // epilogue 2
        float ws0 = 0.f, ws1 = 0.f;
#pragma unroll
        for (int nt = 0; nt < 16; nt++) {
            int c = nt * 8 + 2 * t4;
            ws0 += silu_f(acc[nt][0] + sBc1[c])     * sWc2[c];
            ws0 += silu_f(acc[nt][1] + sBc1[c + 1]) * sWc2[c + 1];
            ws1 += silu_f(acc[nt][2] + sBc1[c])     * sWc2[c];
            ws1 += silu_f(acc[nt][3] + sBc1[c + 1]) * sWc2[c + 1];
        }
        ws0 += __shfl_xor_sync(0xffffffffu, ws0, 1);
        ws0 += __shfl_xor_sync(0xffffffffu, ws0, 2);
        ws1 += __shfl_xor_sync(0xffffffffu, ws1, 1);
        ws1 += __shfl_xor_sync(0xffffffffu, ws1, 2);
        if (t4 == 0) {
            atomicAdd(xo + (size_t)d0 * 3 + 0, rx0 * ws0);
            atomicAdd(xo + (size_t)d0 * 3 + 1, ry0 * ws0);
            atomicAdd(xo + (size_t)d0 * 3 + 2, rz0 * ws0);
            atomicAdd(xo + (size_t)d1 * 3 + 0, rx1 * ws1);
            atomicAdd(xo + (size_t)d1 * 3 + 1, ry1 * ws1);
            atomicAdd(xo + (size_t)d1 * 3 + 2, rz1 * ws1);
        }
    }
}

// ---------------------------------------------------------------------------
// tensor node kernel: h_out = h + Wn2 @ SiLU([h|msg]@Wn1 + bn1) + bn2
__global__ __launch_bounds__(32 * EWARPS) void node_kernel_mma(
    const float* __restrict__ h,
    const float* __restrict__ bn1, const float* __restrict__ bn2,
    float* __restrict__ ho)
{
    extern __shared__ unsigned su[];
    float* sBn1 = (float*)(su + 49152);
    float* sBn2 = sBn1 + 128;

    const int tid  = threadIdx.x;
    const int wid  = tid >> 5;
    const int lane = tid & 31;
    const int g    = lane >> 2;
    const int t4   = lane & 3;

    for (int i = tid; i < 32768 / 4; i += 32 * EWARPS)
        cp_async16(su + i * 4, g_Wn1i + i * 4);
    for (int i = tid; i < 16384 / 4; i += 32 * EWARPS)
        cp_async16(su + 32768 + i * 4, g_Wn2i + i * 4);
    cp_commit();
    if (tid < 128) { sBn1[tid] = bn1[tid]; sBn2[tid] = bn2[tid]; }
    cp_wait<0>();
    __syncthreads();

    for (int wt = blockIdx.x * EWARPS + wid; wt < NNT; wt += EGRID * EWARPS) {
        const int na = wt * 16 + g;
        const int nb = na + 8;
        const float* pa = h + (size_t)na * Hh;
        const float* pb = h + (size_t)nb * Hh;
        const float* ma = g_msg + (size_t)na * Hh;
        const float* mb = g_msg + (size_t)nb * Hh;

        float acc[16][4];
#pragma unroll
        for (int nt = 0; nt < 16; nt++)
#pragma unroll
            for (int j = 0; j < 4; j++) acc[nt][j] = 0.f;

        // GEMM1, K=256 streamed (h part then msg part), interleaved B
        float4 va = *(const float4*)(pa + 4 * t4);
        float4 vb = *(const float4*)(pb + 4 * t4);
#pragma unroll
        for (int kt = 0; kt < 16; kt++) {
            float4 ca = va, cb = vb;
            if (kt < 7) {
                va = *(const float4*)(pa + (kt + 1) * 16 + 4 * t4);
                vb = *(const float4*)(pb + (kt + 1) * 16 + 4 * t4);
            } else if (kt < 15) {
                va = *(const float4*)(ma + (kt - 7) * 16 + 4 * t4);
                vb = *(const float4*)(mb + (kt - 7) * 16 + 4 * t4);
            }
            unsigned aH[4], aL[4];
            split2(ca.x, ca.y, aH[0], aL[0]);
            split2(ca.z, ca.w, aH[2], aL[2]);
            split2(cb.x, cb.y, aH[1], aL[1]);
            split2(cb.z, cb.w, aH[3], aL[3]);
            const unsigned* bi = su + kt * 2048 + lane * 4;
#pragma unroll
            for (int nt = 0; nt < 16; nt++) {
                uint4 b = *(const uint4*)(bi + nt * 128);
                mma_bf16(acc[nt], aH, b.x, b.y);
                mma_bf16(acc[nt], aH, b.z, b.w);
                mma_bf16(acc[nt], aL, b.x, b.y);
            }
        }

        // silu(C1 + bn1), repack
        unsigned aHi[8][4], aLo[8][4];
#pragma unroll
        for (int kt = 0; kt < 8; kt++) {
            int c = kt * 16 + 2 * t4;
            float m00 = silu_f(acc[2 * kt][0]     + sBn1[c]);
            float m01 = silu_f(acc[2 * kt][1]     + sBn1[c + 1]);
            float m10 = silu_f(acc[2 * kt][2]     + sBn1[c]);
            float m11 = silu_f(acc[2 * kt][3]     + sBn1[c + 1]);
            float m02 = silu_f(acc[2 * kt + 1][0] + sBn1[c + 8]);
            float m03 = silu_f(acc[2 * kt + 1][1] + sBn1[c + 9]);
            float m12 = silu_f(acc[2 * kt + 1][2] + sBn1[c + 8]);
            float m13 = silu_f(acc[2 * kt + 1][3] + sBn1[c + 9]);
            split2(m00, m01, aHi[kt][0], aLo[kt][0]);
            split2(m10, m11, aHi[kt][1], aLo[kt][1]);
            split2(m02, m03, aHi[kt][2], aLo[kt][2]);
            split2(m12, m13, aHi[kt][3], aLo[kt][3]);
        }

        // GEMM2 (Wn2 interleaved, 3-pass)
#pragma unroll
        for (int nt = 0; nt < 16; nt++)
#pragma unroll
            for (int j = 0; j < 4; j++) acc[nt][j] = 0.f;
#pragma unroll
        for (int kt = 0; kt < 8; kt++) {
            const unsigned* bi = su + 32768 + kt * 2048 + lane * 4;
#pragma unroll
            for (int nt = 0; nt < 16; nt++) {
                uint4 b = *(const uint4*)(bi + nt * 128);
                mma_bf16(acc[nt], aHi[kt], b.x, b.y);
                mma_bf16(acc[nt], aHi[kt], b.z, b.w);
                mma_bf16(acc[nt], aLo[kt], b.x, b.y);
            }
        }

        // final: + bn2 + h
#pragma unroll
        for (int nt = 0; nt < 16; nt++) {
            int c = nt * 8 + 2 * t4;
            float2 h0 = *(const float2*)(pa + c);
            float2 h1 = *(const float2*)(pb + c);
            float2 o0, o1;
            o0.x = acc[nt][0] + sBn2[c]     + h0.x;
            o0.y = acc[nt][1] + sBn2[c + 1] + h0.y;
            o1.x = acc[nt][2] + sBn2[c]     + h1.x;
            o1.y = acc[nt][3] + sBn2[c + 1] + h1.y;
            *(float2*)(ho + (size_t)na * Hh + c) = o0;
            *(float2*)(ho + (size_t)nb * Hh + c) = o1;
        }
    }
}

// ---------------------------------------------------------------------------
static const int PRE_SMEM_M  = 32768 * 4 + 128 * 4;            // 131584
static const int EDGE_SMEM_M = SM_META_E * 4 + 4 * 128 * 4;    // 100352
static const int NODE_SMEM_M = 49152 * 4 + 2 * 128 * 4;        // 197632

extern "C" void kernel_launch(void* const* d_in, const int* in_sizes, int n_in,
                              void* d_out, int out_size) {
    const float* h   = (const float*)d_in[0];
    const float* x   = (const float*)d_in[1];
    const int*   ei  = (const int*)d_in[2];
    const float* We1 = (const float*)d_in[3];
    const float* be1 = (const float*)d_in[4];
    const float* We2 = (const float*)d_in[5];
    const float* be2 = (const float*)d_in[6];
    const float* Wc1 = (const float*)d_in[7];
    const float* bc1 = (const float*)d_in[8];
    const float* Wc2 = (const float*)d_in[9];
    const float* Wn1 = (const float*)d_in[10];
    const float* bn1 = (const float*)d_in[11];
    const float* Wn2 = (const float*)d_in[12];
    const float* bn2 = (const float*)d_in[13];

    float* out = (float*)d_out;
    float* ho = out;                         // h_out: N*H
    float* xo = out + (size_t)Nn * Hh;       // x_out: N*3

    cudaFuncSetAttribute(pre_kernel_mma,  cudaFuncAttributeMaxDynamicSharedMemorySize, PRE_SMEM_M);
    cudaFuncSetAttribute(edge_kernel_mma, cudaFuncAttributeMaxDynamicSharedMemorySize, EDGE_SMEM_M);
    cudaFuncSetAttribute(node_kernel_mma, cudaFuncAttributeMaxDynamicSharedMemorySize, NODE_SMEM_M);

    init_kernel<<<(Nn * Hh + 255) / 256, 256>>>(x, xo);
    prep_edge_kernel<<<64, 256>>>(We2, Wc1);
    prep_node_kernel<<<96, 256>>>(Wn1, Wn2);
    prep_pre_kernel<<<64, 256>>>(We1);
    pre_kernel_mma<<<EGRID, 32 * EWARPS, PRE_SMEM_M>>>(h, be1);
    edge_kernel_mma<<<EGRID, 32 * EWARPS, EDGE_SMEM_M>>>(x, ei, We1, be2, bc1, Wc2, xo);
    node_kernel_mma<<<EGRID, 32 * EWARPS, NODE_SMEM_M>>>(h, bn1, bn2, ho);
}

// round 17
// speedup vs baseline: 1.4038x; 1.4038x over previous
#include <cuda_runtime.h>
#include <cuda_bf16.h>

#define Nn 50000
#define Ee 640000
#define Hh 128
#define CHUNK 16
#define NWT 40000            // Ee / 16 edge warp-tiles
#define EGRID 148
#define EWARPS 12
#define NNT 3125             // Nn / 16 node warp-tiles

// ---------------- device-global scratch (no allocs allowed) ----------------
__device__ __align__(16) float g_msg[Nn * Hh];
__device__ __align__(16) float g_hs[Nn * Hh];   // h @ We1[0:128] + be1
__device__ __align__(16) float g_hd[Nn * Hh];   // h @ We1[128:256]
// edge B images (mma fragment order): 0 = We2^T hi (PERM-K), 1 = We2^T lo (PERM-K),
// 2 = Wc1^T hi (natural), 3 = Wc1^T lo (unused)
__device__ __align__(16) unsigned g_Bfrag[4][8192];
// node B images: [0:16384) Wn1 hi (PERM-K, K=256), [16384:32768) Wn1 lo,
// [32768:40960) Wn2 hi (natural), [40960:49152) Wn2 lo
__device__ __align__(16) unsigned g_BfragN[49152];

__device__ __forceinline__ float silu_f(float v) {
    return __fdividef(v, 1.f + __expf(-v));
}

union U64F2 { unsigned long long u; float2 f; };

// ---------------- cp.async ----------------
__device__ __forceinline__ void cp_async16(void* dst, const void* src) {
    unsigned u = (unsigned)__cvta_generic_to_shared(dst);
    asm volatile("cp.async.ca.shared.global [%0], [%1], 16;" :: "r"(u), "l"(src));
}
__device__ __forceinline__ void cp_commit() { asm volatile("cp.async.commit_group;"); }
template<int P> __device__ __forceinline__ void cp_wait() {
    asm volatile("cp.async.wait_group %0;" :: "n"(P));
}

// ---------------- warp mma ----------------
__device__ __forceinline__ void mma_bf16(float* c, const unsigned* a,
                                         unsigned b0, unsigned b1) {
    asm volatile(
        "mma.sync.aligned.m16n8k16.row.col.f32.bf16.bf16.f32 "
        "{%0,%1,%2,%3}, {%4,%5,%6,%7}, {%8,%9}, {%0,%1,%2,%3};"
        : "+f"(c[0]), "+f"(c[1]), "+f"(c[2]), "+f"(c[3])
        : "r"(a[0]), "r"(a[1]), "r"(a[2]), "r"(a[3]), "r"(b0), "r"(b1));
}

__device__ __forceinline__ unsigned pack_bf2(float x, float y) {
    __nv_bfloat162 t = __floats2bfloat162_rn(x, y);
    return *(unsigned*)&t;
}
__device__ __forceinline__ void split2(float x, float y, unsigned& hi, unsigned& lo) {
    __nv_bfloat16 hx = __float2bfloat16(x), hy = __float2bfloat16(y);
    hi = (unsigned)__bfloat16_as_ushort(hx) | ((unsigned)__bfloat16_as_ushort(hy) << 16);
    lo = pack_bf2(x - __bfloat162float(hx), y - __bfloat162float(hy));
}

// ---------------------------------------------------------------------------
__global__ void init_kernel(const float* __restrict__ x, float* __restrict__ xo) {
    int idx = blockIdx.x * 256 + threadIdx.x;
    if (idx < Nn * 3) xo[idx] = x[idx];
    if (idx < Nn * Hh) g_msg[idx] = 0.f;
}

// K-permutation note: MMA result is invariant when A and B use the same K
// reorder. Perm p (within each 16-col kt block): frag pos 2*t4+j <-> orig
// 4*t4+j ; frag pos 8+2*t4+j <-> orig 4*t4+2+j. This makes each lane's 4
// A-values per kt one contiguous float4 at orig col kt*16+4*t4.

// edge weights: We2 (perm-K), Wc1 (natural)
__global__ void prep_kernel(const float* __restrict__ We2, const float* __restrict__ Wc1) {
    int idx = blockIdx.x * 256 + threadIdx.x;
    if (idx >= 16384) return;
    int reg  = idx & 1;
    int lane = (idx >> 1) & 31;
    int nt   = (idx >> 6) & 15;
    int kt   = (idx >> 10) & 7;
    int mat  = idx >> 13;
    const float* W = mat ? Wc1 : We2;
    int n  = nt * 8 + (lane >> 2);
    int k0 = mat ? (kt * 16 + reg * 8 + (lane & 3) * 2)      // natural (Wc1)
                 : (kt * 16 + (lane & 3) * 4 + reg * 2);     // perm (We2)
    float w0 = W[k0 * Hh + n];
    float w1 = W[(k0 + 1) * Hh + n];
    unsigned hi, lo;
    split2(w0, w1, hi, lo);
    int off = kt * 1024 + nt * 64 + lane * 2 + reg;
    g_Bfrag[mat * 2 + 0][off] = hi;
    g_Bfrag[mat * 2 + 1][off] = lo;
}

// node weights: Wn1 (perm-K over K=256), Wn2 (natural)
__global__ void prep_node_kernel(const float* __restrict__ Wn1, const float* __restrict__ Wn2) {
    int idx = blockIdx.x * 256 + threadIdx.x;
    if (idx < 16384) {
        int reg = idx & 1, lane = (idx >> 1) & 31, nt = (idx >> 6) & 15, kt = idx >> 10;
        int n  = nt * 8 + (lane >> 2);
        int k0 = kt * 16 + (lane & 3) * 4 + reg * 2;         // perm, k over [0,256)
        float w0 = Wn1[k0 * Hh + n];
        float w1 = Wn1[(k0 + 1) * Hh + n];
        unsigned hi, lo;
        split2(w0, w1, hi, lo);
        int off = kt * 1024 + nt * 64 + lane * 2 + reg;
        g_BfragN[off] = hi;
        g_BfragN[16384 + off] = lo;
    } else if (idx < 24576) {
        int t = idx - 16384;
        int reg = t & 1, lane = (t >> 1) & 31, nt = (t >> 6) & 15, kt = t >> 10;
        int n  = nt * 8 + (lane >> 2);
        int k0 = kt * 16 + reg * 8 + (lane & 3) * 2;         // natural
        float w0 = Wn2[k0 * Hh + n];
        float w1 = Wn2[(k0 + 1) * Hh + n];
        unsigned hi, lo;
        split2(w0, w1, hi, lo);
        int off = kt * 1024 + nt * 64 + lane * 2 + reg;
        g_BfragN[32768 + off] = hi;
        g_BfragN[40960 + off] = lo;
    }
}

// ---------------- SIMT gemm_tile (pre kernel only) ----------------
__device__ __forceinline__ int colof(int tx, int cp) {
    return (cp < 2) ? (tx * 4 + cp * 2) : (64 + tx * 4 + (cp - 2) * 2);
}
__device__ __forceinline__ void stage_b(float* dst, const float* __restrict__ src, int tid) {
#pragma unroll
    for (int s = 0; s < CHUNK / 4; s++) {
        int idx = tid + s * 128;
        int row = idx >> 5, col = (idx & 31) * 4;
        cp_async16(dst + row * 128 + col, src + row * 128 + col);
    }
}
template <int AW, bool ZERO_INIT>
__device__ __forceinline__ void gemm_tile(
    const float* sA, float* sB, const float* __restrict__ Bg, int K,
    int ty, int tx, int tid, unsigned long long acc2[8][4])
{
    if (ZERO_INIT) {
#pragma unroll
        for (int r = 0; r < 8; r++)
#pragma unroll
            for (int cp = 0; cp < 4; cp++) acc2[r][cp] = 0ull;
    }
    const int nCh = K / CHUNK;
    stage_b(sB, Bg, tid);
    cp_commit();
    for (int c = 0; c < nCh; c++) {
        cp_wait<0>();
        __syncthreads();
        if (c + 1 < nCh) {
            stage_b(sB + ((c + 1) & 1) * (CHUNK * 128), Bg + (c + 1) * CHUNK * 128, tid);
            cp_commit();
        }
        const float* A  = sA + (ty * 8) * AW + c * CHUNK;
        const float* Bb = sB + (c & 1) * (CHUNK * 128);
#pragma unroll
        for (int kq = 0; kq < CHUNK / 4; kq++) {
            float4 a4[8];
#pragma unroll
            for (int r = 0; r < 8; r++)
                a4[r] = *(const float4*)(A + r * AW + kq * 4);
#pragma unroll
            for (int k2 = 0; k2 < 4; k2++) {
                const float* brow = Bb + (kq * 4 + k2) * 128;
                ulonglong2 t0 = *(const ulonglong2*)(brow + tx * 4);
                ulonglong2 t1 = *(const ulonglong2*)(brow + 64 + tx * 4);
                unsigned long long b2[4] = { t0.x, t0.y, t1.x, t1.y };
#pragma unroll
                for (int r = 0; r < 8; r++) {
                    float a = (k2 == 0) ? a4[r].x : (k2 == 1) ? a4[r].y
                             : (k2 == 2) ? a4[r].z : a4[r].w;
                    unsigned long long a2;
                    asm("mov.b64 %0, {%1, %1};" : "=l"(a2) : "f"(a));
#pragma unroll
                    for (int cp = 0; cp < 4; cp++)
                        asm("fma.rn.f32x2 %0, %1, %2, %0;"
                            : "+l"(acc2[r][cp]) : "l"(a2), "l"(b2[cp]));
                }
            }
        }
    }
    __syncthreads();
}

// ---------------------------------------------------------------------------
// precompute: g_hs = h @ We1[0:128] + be1 ; g_hd = h @ We1[128:256]
__global__ __launch_bounds__(128, 3) void pre_kernel(
    const float* __restrict__ h, const float* __restrict__ We1,
    const float* __restrict__ be1)
{
    const int AW = 132;
    extern __shared__ float sm[];
    float* sA = sm;
    float* sB = sm + 64 * AW;
    int tid = threadIdx.x;
    int ty = tid >> 4, tx = tid & 15;
    int n0 = blockIdx.x * 64;

    for (int idx = tid; idx < 64 * 32; idx += 128) {
        int i = idx >> 5, q = (idx & 31) * 4;
        int n = n0 + i;
        float4 v = make_float4(0.f, 0.f, 0.f, 0.f);
        if (n < Nn) v = *(const float4*)(h + (size_t)n * Hh + q);
        *(float4*)(sA + i * AW + q) = v;
    }

    unsigned long long acc2[8][4];
    gemm_tile<AW, true>(sA, sB, We1, Hh, ty, tx, tid, acc2);
#pragma unroll
    for (int r = 0; r < 8; r++) {
        int n = n0 + ty * 8 + r;
        if (n < Nn) {
#pragma unroll
            for (int cp = 0; cp < 4; cp++) {
                U64F2 u; u.u = acc2[r][cp];
                int f = colof(tx, cp);
                float2 o; o.x = u.f.x + be1[f]; o.y = u.f.y + be1[f + 1];
                *(float2*)(g_hs + (size_t)n * Hh + f) = o;
            }
        }
    }
    gemm_tile<AW, true>(sA, sB, We1 + 128 * Hh, Hh, ty, tx, tid, acc2);
#pragma unroll
    for (int r = 0; r < 8; r++) {
        int n = n0 + ty * 8 + r;
        if (n < Nn) {
#pragma unroll
            for (int cp = 0; cp < 4; cp++) {
                U64F2 u; u.u = acc2[r][cp];
                *(float2*)(g_hd + (size_t)n * Hh + colof(tx, cp)) = u.f;
            }
        }
    }
}

// ---------------------------------------------------------------------------
// tensor edge kernel: warp-autonomous, 12 warps. GEMM1 perm-K float4 gathers.
#define SB_U32   8192
#define SM_META  (3 * SB_U32)
__global__ __launch_bounds__(32 * EWARPS) void edge_kernel_mma(
    const float* __restrict__ x, const int* __restrict__ ei,
    const float* __restrict__ We1,
    const float* __restrict__ be2, const float* __restrict__ bc1,
    const float* __restrict__ Wc2, float* __restrict__ xo)
{
    extern __shared__ unsigned su[];
    float* sW256 = (float*)(su + SM_META);
    float* sBe2  = sW256 + 128;
    float* sBc1  = sBe2 + 128;
    float* sWc2  = sBc1 + 128;

    const int tid  = threadIdx.x;
    const int wid  = tid >> 5;
    const int lane = tid & 31;
    const int g    = lane >> 2;
    const int t4   = lane & 3;

    for (int i = tid; i < 3 * SB_U32 / 4; i += 32 * EWARPS)
        cp_async16(su + i * 4, (const unsigned*)g_Bfrag + i * 4);
    cp_commit();
    if (tid < 128) {
        sW256[tid] = We1[256 * Hh + tid];
        sBe2[tid]  = be2[tid];
        sBc1[tid]  = bc1[tid];
        sWc2[tid]  = Wc2[tid];
    }
    cp_wait<0>();
    __syncthreads();

    const int gwarp = blockIdx.x * EWARPS + wid;

    for (int wt = gwarp; wt < NWT; wt += EGRID * EWARPS) {
        const int ge0 = wt * 16 + g;
        const int ge1 = ge0 + 8;
        const int s0 = ei[ge0], d0 = ei[Ee + ge0];
        const int s1 = ei[ge1], d1 = ei[Ee + ge1];
        float rx0 = x[s0 * 3 + 0] - x[d0 * 3 + 0];
        float ry0 = x[s0 * 3 + 1] - x[d0 * 3 + 1];
        float rz0 = x[s0 * 3 + 2] - x[d0 * 3 + 2];
        float rx1 = x[s1 * 3 + 0] - x[d1 * 3 + 0];
        float ry1 = x[s1 * 3 + 1] - x[d1 * 3 + 1];
        float rz1 = x[s1 * 3 + 2] - x[d1 * 3 + 2];
        const float d2_0 = rx0 * rx0 + ry0 * ry0 + rz0 * rz0;
        const float d2_1 = rx1 * rx1 + ry1 * ry1 + rz1 * rz1;

        // ---- layer-1 gather: one float4 per (kt, src) per row (perm-K) ----
        unsigned aHi[8][4], aLo[8][4];
        {
            float4 s4[8], d4[8];
#pragma unroll
            for (int kt = 0; kt < 8; kt++) {
                s4[kt] = *(const float4*)(g_hs + (size_t)s0 * Hh + kt * 16 + 4 * t4);
                d4[kt] = *(const float4*)(g_hd + (size_t)d0 * Hh + kt * 16 + 4 * t4);
            }
#pragma unroll
            for (int kt = 0; kt < 8; kt++) {
                float4 w = *(const float4*)(sW256 + kt * 16 + 4 * t4);
                split2(silu_f(s4[kt].x + d4[kt].x + d2_0 * w.x),
                       silu_f(s4[kt].y + d4[kt].y + d2_0 * w.y), aHi[kt][0], aLo[kt][0]);
                split2(silu_f(s4[kt].z + d4[kt].z + d2_0 * w.z),
                       silu_f(s4[kt].w + d4[kt].w + d2_0 * w.w), aHi[kt][2], aLo[kt][2]);
            }
#pragma unroll
            for (int kt = 0; kt < 8; kt++) {
                s4[kt] = *(const float4*)(g_hs + (size_t)s1 * Hh + kt * 16 + 4 * t4);
                d4[kt] = *(const float4*)(g_hd + (size_t)d1 * Hh + kt * 16 + 4 * t4);
            }
#pragma unroll
            for (int kt = 0; kt < 8; kt++) {
                float4 w = *(const float4*)(sW256 + kt * 16 + 4 * t4);
                split2(silu_f(s4[kt].x + d4[kt].x + d2_1 * w.x),
                       silu_f(s4[kt].y + d4[kt].y + d2_1 * w.y), aHi[kt][1], aLo[kt][1]);
                split2(silu_f(s4[kt].z + d4[kt].z + d2_1 * w.z),
                       silu_f(s4[kt].w + d4[kt].w + d2_1 * w.w), aHi[kt][3], aLo[kt][3]);
            }
        }

        // ---- GEMM1 (perm-K B images): 3-pass split ----
        float acc[16][4];
#pragma unroll
        for (int nt = 0; nt < 16; nt++)
#pragma unroll
            for (int j = 0; j < 4; j++) acc[nt][j] = 0.f;
#pragma unroll
        for (int kt = 0; kt < 8; kt++) {
            const unsigned* bh = su + 0 * SB_U32 + kt * 1024 + lane * 2;
            const unsigned* bl = su + 1 * SB_U32 + kt * 1024 + lane * 2;
#pragma unroll
            for (int nt = 0; nt < 16; nt++) {
                uint2 bH = *(const uint2*)(bh + nt * 64);
                uint2 bL = *(const uint2*)(bl + nt * 64);
                mma_bf16(acc[nt], aHi[kt], bH.x, bH.y);
                mma_bf16(acc[nt], aHi[kt], bL.x, bL.y);
                mma_bf16(acc[nt], aLo[kt], bH.x, bH.y);
            }
        }

        // ---- epilogue 1 (C cols are natural): silu, scatter, repack ----
        float* msg0 = g_msg + (size_t)d0 * Hh;
        float* msg1 = g_msg + (size_t)d1 * Hh;
#pragma unroll
        for (int kt = 0; kt < 8; kt++) {
            int c = kt * 16 + 2 * t4;
            float m00 = silu_f(acc[2 * kt][0]     + sBe2[c]);
            float m01 = silu_f(acc[2 * kt][1]     + sBe2[c + 1]);
            float m10 = silu_f(acc[2 * kt][2]     + sBe2[c]);
            float m11 = silu_f(acc[2 * kt][3]     + sBe2[c + 1]);
            float m02 = silu_f(acc[2 * kt + 1][0] + sBe2[c + 8]);
            float m03 = silu_f(acc[2 * kt + 1][1] + sBe2[c + 9]);
            float m12 = silu_f(acc[2 * kt + 1][2] + sBe2[c + 8]);
            float m13 = silu_f(acc[2 * kt + 1][3] + sBe2[c + 9]);
            asm volatile("red.global.add.v2.f32 [%0], {%1, %2};"
                         :: "l"(msg0 + c),     "f"(m00), "f"(m01) : "memory");
            asm volatile("red.global.add.v2.f32 [%0], {%1, %2};"
                         :: "l"(msg0 + c + 8), "f"(m02), "f"(m03) : "memory");
            asm volatile("red.global.add.v2.f32 [%0], {%1, %2};"
                         :: "l"(msg1 + c),     "f"(m10), "f"(m11) : "memory");
            asm volatile("red.global.add.v2.f32 [%0], {%1, %2};"
                         :: "l"(msg1 + c + 8), "f"(m12), "f"(m13) : "memory");
            split2(m00, m01, aHi[kt][0], aLo[kt][0]);
            split2(m10, m11, aHi[kt][1], aLo[kt][1]);
            split2(m02, m03, aHi[kt][2], aLo[kt][2]);
            split2(m12, m13, aHi[kt][3], aLo[kt][3]);
        }

        // ---- GEMM2 (natural B, identity chaining): 2-pass ----
#pragma unroll
        for (int nt = 0; nt < 16; nt++)
#pragma unroll
            for (int j = 0; j < 4; j++) acc[nt][j] = 0.f;
#pragma unroll
        for (int kt = 0; kt < 8; kt++) {
            const unsigned* bh = su + 2 * SB_U32 + kt * 1024 + lane * 2;
#pragma unroll
            for (int nt = 0; nt < 16; nt++) {
                uint2 bH = *(const uint2*)(bh + nt * 64);
                mma_bf16(acc[nt], aHi[kt], bH.x, bH.y);
                mma_bf16(acc[nt], aLo[kt], bH.x, bH.y);
            }
        }

        // ---- epilogue 2 ----
        float ws0 = 0.f, ws1 = 0.f;
#pragma unroll
        for (int nt = 0; nt < 16; nt++) {
            int c = nt * 8 + 2 * t4;
            ws0 += silu_f(acc[nt][0] + sBc1[c])     * sWc2[c];
            ws0 += silu_f(acc[nt][1] + sBc1[c + 1]) * sWc2[c + 1];
            ws1 += silu_f(acc[nt][2] + sBc1[c])     * sWc2[c];
            ws1 += silu_f(acc[nt][3] + sBc1[c + 1]) * sWc2[c + 1];
        }
        ws0 += __shfl_xor_sync(0xffffffffu, ws0, 1);
        ws0 += __shfl_xor_sync(0xffffffffu, ws0, 2);
        ws1 += __shfl_xor_sync(0xffffffffu, ws1, 1);
        ws1 += __shfl_xor_sync(0xffffffffu, ws1, 2);
        if (t4 == 0) {
            atomicAdd(xo + (size_t)d0 * 3 + 0, rx0 * ws0);
            atomicAdd(xo + (size_t)d0 * 3 + 1, ry0 * ws0);
            atomicAdd(xo + (size_t)d0 * 3 + 2, rz0 * ws0);
            atomicAdd(xo + (size_t)d1 * 3 + 0, rx1 * ws1);
            atomicAdd(xo + (size_t)d1 * 3 + 1, ry1 * ws1);
            atomicAdd(xo + (size_t)d1 * 3 + 2, rz1 * ws1);
        }
    }
}

// ---------------------------------------------------------------------------
// tensor node kernel: h_out = h + Wn2 @ SiLU([h|msg]@Wn1 + bn1) + bn2
__global__ __launch_bounds__(32 * EWARPS) void node_kernel_mma(
    const float* __restrict__ h,
    const float* __restrict__ bn1, const float* __restrict__ bn2,
    float* __restrict__ ho)
{
    extern __shared__ unsigned su[];
    float* sBn1 = (float*)(su + 49152);
    float* sBn2 = sBn1 + 128;

    const int tid  = threadIdx.x;
    const int wid  = tid >> 5;
    const int lane = tid & 31;
    const int g    = lane >> 2;
    const int t4   = lane & 3;

    for (int i = tid; i < 49152 / 4; i += 32 * EWARPS)
        cp_async16(su + i * 4, g_BfragN + i * 4);
    cp_commit();
    if (tid < 128) { sBn1[tid] = bn1[tid]; sBn2[tid] = bn2[tid]; }
    cp_wait<0>();
    __syncthreads();

    for (int wt = blockIdx.x * EWARPS + wid; wt < NNT; wt += EGRID * EWARPS) {
        const int na = wt * 16 + g;
        const int nb = na + 8;
        const float* pa = h + (size_t)na * Hh;
        const float* pb = h + (size_t)nb * Hh;
        const float* ma = g_msg + (size_t)na * Hh;
        const float* mb = g_msg + (size_t)nb * Hh;

        float acc[16][4];
#pragma unroll
        for (int nt = 0; nt < 16; nt++)
#pragma unroll
            for (int j = 0; j < 4; j++) acc[nt][j] = 0.f;

        // GEMM1, K=256 streamed with 1-deep prefetch (h part then msg part)
        float4 va = *(const float4*)(pa + 4 * t4);
        float4 vb = *(const float4*)(pb + 4 * t4);
#pragma unroll
        for (int kt = 0; kt < 16; kt++) {
            float4 ca = va, cb = vb;
            if (kt < 7) {
                va = *(const float4*)(pa + (kt + 1) * 16 + 4 * t4);
                vb = *(const float4*)(pb + (kt + 1) * 16 + 4 * t4);
            } else if (kt < 15) {
                va = *(const float4*)(ma + (kt - 7) * 16 + 4 * t4);
                vb = *(const float4*)(mb + (kt - 7) * 16 + 4 * t4);
            }
            unsigned aH[4], aL[4];
            split2(ca.x, ca.y, aH[0], aL[0]);
            split2(ca.z, ca.w, aH[2], aL[2]);
            split2(cb.x, cb.y, aH[1], aL[1]);
            split2(cb.z, cb.w, aH[3], aL[3]);
            const unsigned* bh = su + kt * 1024 + lane * 2;
            const unsigned* bl = su + 16384 + kt * 1024 + lane * 2;
#pragma unroll
            for (int nt = 0; nt < 16; nt++) {
                uint2 bH = *(const uint2*)(bh + nt * 64);
                uint2 bL = *(const uint2*)(bl + nt * 64);
                mma_bf16(acc[nt], aH, bH.x, bH.y);
                mma_bf16(acc[nt], aH, bL.x, bL.y);
                mma_bf16(acc[nt], aL, bH.x, bH.y);
            }
        }

        // silu(C1 + bn1), repack (identity chaining)
        unsigned aHi[8][4], aLo[8][4];
#pragma unroll
        for (int kt = 0; kt < 8; kt++) {
            int c = kt * 16 + 2 * t4;
            float m00 = silu_f(acc[2 * kt][0]     + sBn1[c]);
            float m01 = silu_f(acc[2 * kt][1]     + sBn1[c + 1]);
            float m10 = silu_f(acc[2 * kt][2]     + sBn1[c]);
            float m11 = silu_f(acc[2 * kt][3]     + sBn1[c + 1]);
            float m02 = silu_f(acc[2 * kt + 1][0] + sBn1[c + 8]);
            float m03 = silu_f(acc[2 * kt + 1][1] + sBn1[c + 9]);
            float m12 = silu_f(acc[2 * kt + 1][2] + sBn1[c + 8]);
            float m13 = silu_f(acc[2 * kt + 1][3] + sBn1[c + 9]);
            split2(m00, m01, aHi[kt][0], aLo[kt][0]);
            split2(m10, m11, aHi[kt][1], aLo[kt][1]);
            split2(m02, m03, aHi[kt][2], aLo[kt][2]);
            split2(m12, m13, aHi[kt][3], aLo[kt][3]);
        }

        // GEMM2 (Wn2, natural): 3-pass
#pragma unroll
        for (int nt = 0; nt < 16; nt++)
#pragma unroll
            for (int j = 0; j < 4; j++) acc[nt][j] = 0.f;
#pragma unroll
        for (int kt = 0; kt < 8; kt++) {
            const unsigned* bh = su + 32768 + kt * 1024 + lane * 2;
            const unsigned* bl = su + 40960 + kt * 1024 + lane * 2;
#pragma unroll
            for (int nt = 0; nt < 16; nt++) {
                uint2 bH = *(const uint2*)(bh + nt * 64);
                uint2 bL = *(const uint2*)(bl + nt * 64);
                mma_bf16(acc[nt], aHi[kt], bH.x, bH.y);
                mma_bf16(acc[nt], aHi[kt], bL.x, bL.y);
                mma_bf16(acc[nt], aLo[kt], bH.x, bH.y);
            }
        }

        // final: + bn2 + h, write h_out
#pragma unroll
        for (int nt = 0; nt < 16; nt++) {
            int c = nt * 8 + 2 * t4;
            float2 h0 = *(const float2*)(pa + c);
            float2 h1 = *(const float2*)(pb + c);
            float2 o0, o1;
            o0.x = acc[nt][0] + sBn2[c]     + h0.x;
            o0.y = acc[nt][1] + sBn2[c + 1] + h0.y;
            o1.x = acc[nt][2] + sBn2[c]     + h1.x;
            o1.y = acc[nt][3] + sBn2[c + 1] + h1.y;
            *(float2*)(ho + (size_t)na * Hh + c) = o0;
            *(float2*)(ho + (size_t)nb * Hh + c) = o1;
        }
    }
}

// ---------------------------------------------------------------------------
static const int PRE_SMEM    = (64 * 132 + 2 * CHUNK * 128) * 4;
static const int EDGE_SMEM_M = 3 * 8192 * 4 + 4 * 128 * 4;
static const int NODE_SMEM_M = 49152 * 4 + 2 * 128 * 4;    // 197632

extern "C" void kernel_launch(void* const* d_in, const int* in_sizes, int n_in,
                              void* d_out, int out_size) {
    const float* h   = (const float*)d_in[0];
    const float* x   = (const float*)d_in[1];
    const int*   ei  = (const int*)d_in[2];
    const float* We1 = (const float*)d_in[3];
    const float* be1 = (const float*)d_in[4];
    const float* We2 = (const float*)d_in[5];
    const float* be2 = (const float*)d_in[6];
    const float* Wc1 = (const float*)d_in[7];
    const float* bc1 = (const float*)d_in[8];
    const float* Wc2 = (const float*)d_in[9];
    const float* Wn1 = (const float*)d_in[10];
    const float* bn1 = (const float*)d_in[11];
    const float* Wn2 = (const float*)d_in[12];
    const float* bn2 = (const float*)d_in[13];

    float* out = (float*)d_out;
    float* ho = out;                         // h_out: N*H
    float* xo = out + (size_t)Nn * Hh;       // x_out: N*3

    cudaFuncSetAttribute(pre_kernel,  cudaFuncAttributeMaxDynamicSharedMemorySize, PRE_SMEM);
    cudaFuncSetAttribute(edge_kernel_mma, cudaFuncAttributeMaxDynamicSharedMemorySize, EDGE_SMEM_M);
    cudaFuncSetAttribute(node_kernel_mma, cudaFuncAttributeMaxDynamicSharedMemorySize, NODE_SMEM_M);

    init_kernel<<<(Nn * Hh + 255) / 256, 256>>>(x, xo);
    prep_kernel<<<64, 256>>>(We2, Wc1);
    prep_node_kernel<<<96, 256>>>(Wn1, Wn2);
    pre_kernel<<<(Nn + 63) / 64, 128, PRE_SMEM>>>(h, We1, be1);
    edge_kernel_mma<<<EGRID, 32 * EWARPS, EDGE_SMEM_M>>>(x, ei, We1, be2, bc1, Wc2, xo);
    node_kernel_mma<<<EGRID, 32 * EWARPS, NODE_SMEM_M>>>(h, bn1, bn2, ho);
}